// round 2
// baseline (speedup 1.0000x reference)
#include <cuda_runtime.h>

// Problem constants (fixed shapes)
#define Nn   100000
#define Ee   3200000
#define NNZn 6400000
#define BN_EPS 1e-5

// Scratch (no allocation allowed in kernel_launch)
__device__ __align__(16) float  g_z0[Nn * 16];
__device__ __align__(16) float  g_z1[Nn * 16];
__device__ __align__(16) float  g_acc[Nn * 16];
__device__ double g_stats[32];   // [0:16) sums, [16:32) sum of squares

// ---------------------------------------------------------------------------
// Helpers
// ---------------------------------------------------------------------------
__device__ __forceinline__ void red_v4(float* addr, float4 v) {
    asm volatile("red.global.add.v4.f32 [%0], {%1,%2,%3,%4};"
                 :: "l"(addr), "f"(v.x), "f"(v.y), "f"(v.z), "f"(v.w)
                 : "memory");
}

__device__ __forceinline__ void load16(const float4* __restrict__ p, float f[16]) {
    float4 a = p[0], b = p[1], c = p[2], d = p[3];
    f[0]=a.x; f[1]=a.y; f[2]=a.z; f[3]=a.w;
    f[4]=b.x; f[5]=b.y; f[6]=b.z; f[7]=b.w;
    f[8]=c.x; f[9]=c.y; f[10]=c.z; f[11]=c.w;
    f[12]=d.x; f[13]=d.y; f[14]=d.z; f[15]=d.w;
}

__device__ __forceinline__ void store16(float4* __restrict__ p, const float f[16]) {
    p[0] = make_float4(f[0],  f[1],  f[2],  f[3]);
    p[1] = make_float4(f[4],  f[5],  f[6],  f[7]);
    p[2] = make_float4(f[8],  f[9],  f[10], f[11]);
    p[3] = make_float4(f[12], f[13], f[14], f[15]);
}

// ---------------------------------------------------------------------------
// acc = feat_a @ W_prev + (deg*feat_a) @ W_deg + (b_prev+b_deg+sum b_rad+b_fuse)
// ---------------------------------------------------------------------------
__global__ void k_dense(const float4* __restrict__ fa, const float* __restrict__ deg,
                        const float* __restrict__ Wp, const float* __restrict__ bp,
                        const float* __restrict__ Wd, const float* __restrict__ bd,
                        const float* __restrict__ brad, const float* __restrict__ bf)
{
    __shared__ float sWp[256], sWd[256], sb[16];
    int t = threadIdx.x;
    sWp[t] = Wp[t];
    sWd[t] = Wd[t];
    if (t < 16)
        sb[t] = bp[t] + bd[t] + brad[t] + brad[16 + t] + brad[32 + t] + bf[t];
    __syncthreads();

    int i = blockIdx.x * 256 + t;
    if (i >= Nn) return;

    float f[16];
    load16(fa + (size_t)i * 4, f);
    float dg = deg[i];

    float o[16];
#pragma unroll
    for (int j = 0; j < 16; j++) o[j] = sb[j];
#pragma unroll
    for (int r = 0; r < 16; r++) {
        float c = f[r];
        float cd = c * dg;
#pragma unroll
        for (int j = 0; j < 16; j++)
            o[j] += c * sWp[r * 16 + j] + cd * sWd[r * 16 + j];
    }
    store16((float4*)(g_acc + (size_t)i * 16), o);
}

// ---------------------------------------------------------------------------
// Hop: zout[dst] += zin[src]  (zout must be pre-zeroed)
// ---------------------------------------------------------------------------
__global__ void k_hop(const float4* __restrict__ zin, float* __restrict__ zout,
                      const int* __restrict__ src, const int* __restrict__ dst)
{
    int e = blockIdx.x * 256 + threadIdx.x;
    if (e >= Ee) return;
    int s = src[e], d = dst[e];
    const float4* zi = zin + (size_t)s * 4;
    float4 a = zi[0], b = zi[1], c = zi[2], dd = zi[3];
    float* zo = zout + (size_t)d * 16;
    red_v4(zo,      a);
    red_v4(zo + 4,  b);
    red_v4(zo + 8,  c);
    red_v4(zo + 12, dd);
}

// ---------------------------------------------------------------------------
// acc += z @ W
// ---------------------------------------------------------------------------
__global__ void k_proj(const float4* __restrict__ z, const float* __restrict__ W)
{
    __shared__ float sW[256];
    sW[threadIdx.x] = W[threadIdx.x];
    __syncthreads();

    int i = blockIdx.x * 256 + threadIdx.x;
    if (i >= Nn) return;

    float f[16];
    load16(z + (size_t)i * 4, f);
    float4* accp = (float4*)(g_acc + (size_t)i * 16);
    float o[16];
    load16(accp, o);
#pragma unroll
    for (int r = 0; r < 16; r++) {
        float c = f[r];
#pragma unroll
        for (int j = 0; j < 16; j++)
            o[j] += c * sW[r * 16 + j];
    }
    store16(accp, o);
}

// ---------------------------------------------------------------------------
// SpMM fused with W_fuse: acc[row] += vals[k] * (feat_b[col] @ W_fuse)
// ---------------------------------------------------------------------------
__global__ void k_spmm(const float4* __restrict__ fb, const float* __restrict__ vals,
                       const int* __restrict__ rows, const int* __restrict__ cols,
                       const float* __restrict__ Wf)
{
    __shared__ float sW[256];
    sW[threadIdx.x] = Wf[threadIdx.x];
    __syncthreads();

    int k = blockIdx.x * 256 + threadIdx.x;
    if (k >= NNZn) return;

    int r = rows[k], c = cols[k];
    float v = vals[k];
    float f[16];
    load16(fb + (size_t)c * 4, f);

    float o[16];
#pragma unroll
    for (int j = 0; j < 16; j++) o[j] = 0.f;
#pragma unroll
    for (int i = 0; i < 16; i++) {
        float fi = f[i] * v;
#pragma unroll
        for (int j = 0; j < 16; j++)
            o[j] += fi * sW[i * 16 + j];
    }
    float* accp = g_acc + (size_t)r * 16;
    red_v4(accp,      make_float4(o[0],  o[1],  o[2],  o[3]));
    red_v4(accp + 4,  make_float4(o[4],  o[5],  o[6],  o[7]));
    red_v4(accp + 8,  make_float4(o[8],  o[9],  o[10], o[11]));
    red_v4(accp + 12, make_float4(o[12], o[13], o[14], o[15]));
}

// ---------------------------------------------------------------------------
// ReLU on columns 8..15 (in place) + per-column sum / sumsq into g_stats
// ---------------------------------------------------------------------------
__global__ void k_stats()
{
    int lane = threadIdx.x & 31;
    int col = lane & 15;           // column handled by this thread (stride is mult of 16)
    bool relu = (col >= 8);

    float sum = 0.f, sq = 0.f;
    int total = Nn * 16;
    int stride = blockDim.x * gridDim.x;
    for (int idx = blockIdx.x * blockDim.x + threadIdx.x; idx < total; idx += stride) {
        float x = g_acc[idx];
        if (relu) {
            x = fmaxf(x, 0.f);
            g_acc[idx] = x;
        }
        sum += x;
        sq += x * x;
    }
    // lanes l and l^16 handle the same column
    sum += __shfl_xor_sync(0xffffffff, sum, 16);
    sq  += __shfl_xor_sync(0xffffffff, sq, 16);
    if (lane < 16) {
        atomicAdd(&g_stats[col],      (double)sum);
        atomicAdd(&g_stats[16 + col], (double)sq);
    }
}

// ---------------------------------------------------------------------------
// BatchNorm finalize: out = (acc - mean) * rsqrt(var+eps) * gamma + beta
// ---------------------------------------------------------------------------
__global__ void k_final(float4* __restrict__ out,
                        const float* __restrict__ gamma, const float* __restrict__ beta)
{
    __shared__ float s_scale[16], s_shift[16];
    if (threadIdx.x < 16) {
        int c = threadIdx.x;
        double mean = g_stats[c] / (double)Nn;
        double var  = g_stats[16 + c] / (double)Nn - mean * mean;
        float sc = (float)(1.0 / sqrt(var + (double)BN_EPS)) * gamma[c];
        s_scale[c] = sc;
        s_shift[c] = beta[c] - (float)mean * sc;
    }
    __syncthreads();

    int total4 = Nn * 4;
    int stride = blockDim.x * gridDim.x;
    const float4* acc4 = (const float4*)g_acc;
    for (int idx = blockIdx.x * blockDim.x + threadIdx.x; idx < total4; idx += stride) {
        float4 x = acc4[idx];
        int c = (idx & 3) * 4;
        float4 y;
        y.x = x.x * s_scale[c]     + s_shift[c];
        y.y = x.y * s_scale[c + 1] + s_shift[c + 1];
        y.z = x.z * s_scale[c + 2] + s_shift[c + 2];
        y.w = x.w * s_scale[c + 3] + s_shift[c + 3];
        out[idx] = y;
    }
}

// ---------------------------------------------------------------------------
// Launch
// ---------------------------------------------------------------------------
extern "C" void kernel_launch(void* const* d_in, const int* in_sizes, int n_in,
                              void* d_out, int out_size)
{
    const float* feat_a  = (const float*)d_in[0];
    const float* feat_b  = (const float*)d_in[1];
    const float* deg     = (const float*)d_in[2];
    const float* pm_vals = (const float*)d_in[3];
    const float* W_prev  = (const float*)d_in[4];
    const float* b_prev  = (const float*)d_in[5];
    const float* W_deg   = (const float*)d_in[6];
    const float* b_deg   = (const float*)d_in[7];
    const float* W_rad   = (const float*)d_in[8];
    const float* b_rad   = (const float*)d_in[9];
    const float* W_fuse  = (const float*)d_in[10];
    const float* b_fuse  = (const float*)d_in[11];
    const float* gamma   = (const float*)d_in[12];
    const float* beta    = (const float*)d_in[13];
    const int*   src     = (const int*)d_in[14];
    const int*   dst     = (const int*)d_in[15];
    const int*   pm_rows = (const int*)d_in[16];
    const int*   pm_cols = (const int*)d_in[17];
    (void)in_sizes; (void)n_in; (void)out_size; (void)pm_vals;

    void *z0p, *z1p, *statsp;
    cudaGetSymbolAddress(&z0p, g_z0);
    cudaGetSymbolAddress(&z1p, g_z1);
    cudaGetSymbolAddress(&statsp, g_stats);
    float* z0 = (float*)z0p;
    float* z1 = (float*)z1p;

    const int nb_nodes = (Nn + 255) / 256;
    const int nb_edges = (Ee + 255) / 256;
    const int nb_nnz   = (NNZn + 255) / 256;
    const size_t zbytes = (size_t)Nn * 16 * sizeof(float);

    cudaMemsetAsync(z0p, 0, zbytes);
    cudaMemsetAsync(statsp, 0, 32 * sizeof(double));

    // dense projections (also writes full acc)
    k_dense<<<nb_nodes, 256>>>((const float4*)feat_a, deg, W_prev, b_prev,
                               W_deg, b_deg, b_rad, b_fuse);

    // z1 = hop(feat_a); acc += z1 @ W_rad[0]
    k_hop<<<nb_edges, 256>>>((const float4*)feat_a, z0, src, dst);
    k_proj<<<nb_nodes, 256>>>((const float4*)z0, W_rad);

    // z2 = hop(z1); acc += z2 @ W_rad[1]
    cudaMemsetAsync(z1p, 0, zbytes);
    k_hop<<<nb_edges, 256>>>((const float4*)z0, z1, src, dst);
    k_proj<<<nb_nodes, 256>>>((const float4*)z1, W_rad + 256);

    // z3 = hop(hop(z2)); acc += z3 @ W_rad[2]
    cudaMemsetAsync(z0p, 0, zbytes);
    k_hop<<<nb_edges, 256>>>((const float4*)z1, z0, src, dst);
    cudaMemsetAsync(z1p, 0, zbytes);
    k_hop<<<nb_edges, 256>>>((const float4*)z0, z1, src, dst);
    k_proj<<<nb_nodes, 256>>>((const float4*)z1, W_rad + 512);

    // acc[row] += vals * (feat_b[col] @ W_fuse)
    k_spmm<<<nb_nnz, 256>>>((const float4*)feat_b, pm_vals, pm_rows, pm_cols, W_fuse);

    // relu half + batch stats
    k_stats<<<148 * 8, 256>>>();

    // batchnorm finalize
    k_final<<<148 * 8, 256>>>((float4*)d_out, gamma, beta);
}